// round 10
// baseline (speedup 1.0000x reference)
#include <cuda_runtime.h>
#include <math.h>

// SpikingLayer — bit-exact JAX/XLA replication, 2-lanes-per-neuron split.
// r6 (1-lane, bit-scan conv): PASS 1961us. r9 (local-mem queues): PASS but
// 2467us — regs=255 spills + LDL chains. This version:
//   - lane pairs: even lane = synapse 0, odd = synapse 1. Conv loops merge
//     into ONE warp loop (iters = warp-max queue len). vt = fl(a0+a1) via
//     shfl_xor (commutative -> bit-exact).
//   - spike-age rings in SMEM (132B stride, bank-spread), r9's validated
//     pop/push logic, single synapse per lane.
//   - refractory buf split by slot parity: 25 packed f32x2 pairs per lane
//     (50 regs -> no spill). rs factors from stride-2 rotated smem tables,
//     aligned LDS.64, all indices compile-time (100-step unrolled body).
// Arithmetic sequence identical to r6/r9: oldest-first FADD conv fold, ghost
// folds add K[127]=0 (exact no-op), chronological per-slot fl(acc+fl(n*rs)),
// op-for-op spike function with straight-through perturbation.

#define T_STEPS 1024
#define BATCH   16
#define NSYN    2
#define NNEU    2048
#define BN      (BATCH * NNEU)          // 32768 neurons
#define TSTRIDE (BATCH * NSYN * NNEU)   // 65536 floats per timestep
#define PF      4
#define RINGSTRIDE 132                  // 128 entries + 4B pad (bank spread)

__global__ __launch_bounds__(128, 3)
void spiking_layer_split(const float* __restrict__ in,
                         const float* __restrict__ epsp,   // (2, 100)
                         const float* __restrict__ refk,   // (100,)
                         float* __restrict__ out)
{
    __shared__ __align__(16) float K0[128];       // taps syn0, K0[127]=0 pad
    __shared__ __align__(16) float K1[128];       // taps syn1
    // G[q][r][i] = rs[(2*(i+r)+q) % 100], rs[k] = -refk[k+1], rs[99] = 0.
    // Stride-2 doubled+rotated tables so the per-lane slot sweep reads
    // aligned float2 pairs. Rows 8B-aligned (104 even).
    __shared__ __align__(8) float G[2][2][104];
    __shared__ unsigned char ring[128 * RINGSTRIDE];  // spike-age ring / lane

    const int tid = threadIdx.x;
    {
        K0[tid] = (tid < 100) ? epsp[tid] : 0.0f;
        K1[tid] = (tid < 100) ? epsp[100 + tid] : 0.0f;
    }
    for (int i = tid; i < 2 * 2 * 104; i += 128) {
        int q = i / (2 * 104), rem = i % (2 * 104);
        int r = rem / 104, ii = rem % 104;
        int k = (2 * (ii + r) + q) % 100;
        G[q][r][ii] = (k < 99) ? -refk[k + 1] : 0.0f;
    }
    __syncthreads();

    const int par = tid & 1;                          // my synapse
    const int nid = (blockIdx.x * 128 + tid) >> 1;    // my neuron
    const int b = nid >> 11;
    const int n = nid & (NNEU - 1);
    const float* px = in + (size_t)b * (NSYN * NNEU) + (size_t)par * NNEU + n;
    float* po = out + nid;
    const float* Kp = par ? K1 : K0;
    unsigned char* myring = ring + tid * RINGSTRIDE;

    // my refractory slots: s = 2m + par, m=0..49; pair j = (m=2j lo, m=2j+1 hi)
    unsigned long long bufp[25];
#pragma unroll
    for (int m = 0; m < 25; m++) bufp[m] = 0ull;

    // spike-age ring state (single synapse); garbage beyond len is guarded
    int h = 0, tq = 0, len = 0, head = 0;

    float xb[PF];
#pragma unroll
    for (int i = 0; i < PF; i++) xb[i] = __ldcs(px + (size_t)i * TSTRIDE);

    auto step = [&](int t, int c) {
        const int i4 = c & (PF - 1);
        const float x = xb[i4];
        if (t + PF < T_STEPS) xb[i4] = __ldcs(px + (size_t)(t + PF) * TSTRIDE);
        const int t8 = t & 255;

        // pop expired head (lag >= 100); at most one per step
        {
            int lagh = (t8 - head) & 255;
            int pop  = (len > 0) & (lagh >= 100);
            int nxt  = myring[(h + 1) & 127];
            h += pop; len -= pop;
            head = pop ? nxt : head;
        }
        // push current spike (unconditional store, guarded slot)
        {
            const int s = (x != 0.0f);
            myring[tq & 127] = (unsigned char)t8;
            head = (len == 0 && s) ? t8 : head;
            tq += s; len += s;
        }

        // EPSP conv: my synapse, oldest-first plain-FADD fold (bit-exact);
        // ghost iterations fold Kp[127] = 0 (exact no-op).
        float a = 0.0f;
        {
            const int iters = __reduce_max_sync(0xffffffffu, len);
#pragma unroll 1
            for (int i = 0; i < iters; ++i) {
                int ts = myring[(h + i) & 127];
                int lg = (t8 - ts) & 255;
                lg = (i < len) ? lg : 127;
                a = __fadd_rn(a, Kp[lg]);
            }
        }
        const float ao = __shfl_xor_sync(0xffffffffu, a, 1);
        const float vt = __fadd_rn(a, ao);        // fl(c0+c1), commutative

        // refractory accumulator for slot c (owner parity = c&1)
        const int cpar = c & 1;
        const int jc = c >> 2;
        const int hc = (c >> 1) & 1;
        const unsigned long long pr = bufp[jc];
        const float cand = __uint_as_float(hc ? (unsigned int)(pr >> 32)
                                              : (unsigned int)pr);
        const float cando = __shfl_xor_sync(0xffffffffu, cand, 1);
        const bool owner = (par == cpar);
        const float bacc = owner ? cand : cando;
        const float v = __fadd_rn(vt, bacc);      // v_eff

        // spike function, op-for-op vs reference
        const float nf   = floorf(fmaxf(v, 0.0f));
        const float e    = expf(__fmul_rn(fabsf(__fadd_rn(v, -1.0f)), -2.0f));
        const float sg   = __fmul_rn(2.0f, e);
        const float term = __fmul_rn(sg, v);
        const float nout = __fadd_rn(__fadd_rn(nf, -term), term);

        if (par == 0) __stcs(po + (size_t)t * BN, nout);

        // zero slot c on its owner (becomes slot for t+100; rs[99]=0)
        {
            const unsigned long long zm =
                hc ? 0x00000000FFFFFFFFull : 0xFFFFFFFF00000000ull;
            bufp[jc] = owner ? (pr & zm) : bufp[jc];
        }

        // buf update: my slots s=2m+par get += fl(nout * rs[(s-c-1) mod 100])
        // as packed f32x2. Skipped when no lane fired (exact no-ops).
        if (__any_sync(0xffffffffu, nout != 0.0f)) {
            unsigned long long n2;
            asm("mov.b64 %0, {%1, %2};" : "=l"(n2) : "f"(nout), "f"(nout));
            // compile-time (q, r, base) for each parity
            const int k0A = 99 - c;                    // par 0
            const int qA  = k0A & 1;
            const int i0A = (k0A - qA) >> 1;
            const int rA  = i0A & 1;
            const int k0B = (100 - c) % 100;           // par 1
            const int qB  = k0B & 1;
            const int i0B = (k0B - qB) >> 1;
            const int rB  = i0B & 1;
            const float2* TA = (const float2*)&G[qA][rA][i0A - rA];
            const float2* TB = (const float2*)&G[qB][rB][i0B - rB];
            const float2* Tb = par ? TB : TA;
#pragma unroll
            for (int j = 0; j < 25; ++j) {
                const float2 rv = Tb[j];
                unsigned long long rs2, p2, nb;
                asm("mov.b64 %0, {%1, %2};" : "=l"(rs2) : "f"(rv.x), "f"(rv.y));
                asm("mul.rn.f32x2 %0, %1, %2;" : "=l"(p2) : "l"(n2), "l"(rs2));
                asm("add.rn.f32x2 %0, %1, %2;" : "=l"(nb) : "l"(bufp[j]), "l"(p2));
                bufp[j] = nb;
            }
        }
    };

#pragma unroll 1
    for (int blk = 0; blk < 10; ++blk) {
        const int tb = blk * 100;
#pragma unroll
        for (int i = 0; i < 100; ++i) step(tb + i, i);
    }
#pragma unroll
    for (int i = 0; i < 24; ++i) step(1000 + i, i);
}

extern "C" void kernel_launch(void* const* d_in, const int* in_sizes, int n_in,
                              void* d_out, int out_size)
{
    const float* spikes = (const float*)d_in[0];
    const float* epsp   = (const float*)d_in[1];
    const float* refk   = (const float*)d_in[2];
    float* out = (float*)d_out;

    spiking_layer_split<<<BN * 2 / 128, 128>>>(spikes, epsp, refk, out);
}

// round 16
// speedup vs baseline: 2.1841x; 2.1841x over previous
#include <cuda_runtime.h>
#include <math.h>

// SpikingLayer — bit-exact JAX/XLA replication, two-kernel split.
// History: r6 fused bit-scan 1961us PASS; r9 local queues 2467us (spills);
// r10 lane-split 2695us (duplicated overhead). All three give bit-identical
// rel_err=5.049318e-4 -> the exact-rounding machinery is proven.
// This round: conv is parallel across t — move it OUT of the scan.
//   Kernel A: vt[t][neuron] = fl(c0+c1) via r10's validated lane-per-
//             (neuron,synapse) smem spike-age rings. High warp count.
//   Kernel B: r6's validated scan minus conv: vt from VT, refractory
//             scatter via RSD float4 tables, 25 packed f32x2 pairs.

#define T_STEPS 1024
#define BATCH   16
#define NSYN    2
#define NNEU    2048
#define BN      (BATCH * NNEU)          // 32768 neurons
#define TSTRIDE (BATCH * NSYN * NNEU)   // 65536 floats per timestep
#define PFA     4                       // kernel A prefetch
#define PFB     8                       // kernel B prefetch
#define RINGSTRIDE 132

__device__ static float VT[(size_t)T_STEPS * BN];   // 128 MB scratch

// ---------------------------------------------------------------- kernel A
__global__ __launch_bounds__(128)
void conv_kernel(const float* __restrict__ in,
                 const float* __restrict__ epsp,   // (2, 100)
                 float* __restrict__ vt_out)
{
    __shared__ __align__(16) float K0[128];   // taps syn0, [127]=0 pad
    __shared__ __align__(16) float K1[128];
    __shared__ unsigned char ring[128 * RINGSTRIDE];

    const int tid = threadIdx.x;
    K0[tid] = (tid < 100) ? epsp[tid] : 0.0f;
    K1[tid] = (tid < 100) ? epsp[100 + tid] : 0.0f;
    __syncthreads();

    const int par = tid & 1;                          // my synapse
    const int nid = (blockIdx.x * 128 + tid) >> 1;    // my neuron
    const int b = nid >> 11;
    const int n = nid & (NNEU - 1);
    const float* px = in + (size_t)b * (NSYN * NNEU) + (size_t)par * NNEU + n;
    const float* Kp = par ? K1 : K0;
    unsigned char* myring = ring + tid * RINGSTRIDE;

    int h = 0, tq = 0, len = 0, head = 0;

    float xb[PFA];
#pragma unroll
    for (int i = 0; i < PFA; i++) xb[i] = __ldcs(px + (size_t)i * TSTRIDE);

#pragma unroll 4
    for (int t = 0; t < T_STEPS; ++t) {
        const int i4 = t & (PFA - 1);
        const float x = xb[i4];
        if (t + PFA < T_STEPS) xb[i4] = __ldcs(px + (size_t)(t + PFA) * TSTRIDE);
        const int t8 = t & 255;

        // pop expired head (lag >= 100); at most one per step
        {
            int lagh = (t8 - head) & 255;
            int pop  = (len > 0) & (lagh >= 100);
            int nxt  = myring[(h + 1) & 127];
            h += pop; len -= pop;
            head = pop ? nxt : head;
        }
        // push current spike (unconditional store to guarded slot)
        {
            const int s = (x != 0.0f);
            myring[tq & 127] = (unsigned char)t8;
            head = (len == 0 && s) ? t8 : head;
            tq += s; len += s;
        }

        // oldest-first plain-FADD fold (bit-exact); ghosts add Kp[127]=0
        float a = 0.0f;
        {
            const int iters = __reduce_max_sync(0xffffffffu, len);
#pragma unroll 1
            for (int i = 0; i < iters; ++i) {
                int ts = myring[(h + i) & 127];
                int lg = (t8 - ts) & 255;
                lg = (i < len) ? lg : 127;
                a = __fadd_rn(a, Kp[lg]);
            }
        }
        const float ao = __shfl_xor_sync(0xffffffffu, a, 1);
        if (par == 0)
            __stcs(vt_out + (size_t)t * BN + nid, __fadd_rn(a, ao));
    }
}

// ---------------------------------------------------------------- kernel B
__global__ __launch_bounds__(128, 2)
void scan_kernel(const float* __restrict__ vt_in,
                 const float* __restrict__ refk,   // (100,)
                 float* __restrict__ out)
{
    // RSD[r][i] = rs[(i + r) % 100], doubled+rotated for aligned float4.
    __shared__ __align__(16) float RSD[4][200];
    const int tid = threadIdx.x;
    for (int i = tid; i < 4 * 200; i += 128) {
        int rr = i / 200, ii = i % 200;
        int k = (ii + rr) % 100;
        RSD[rr][ii] = (k < 99) ? -refk[k + 1] : 0.0f;
    }
    __syncthreads();

    const int g = blockIdx.x * 128 + tid;       // neuron id
    const float* pv = vt_in + g;
    float* po = out + g;

    unsigned long long bufp[50];
#pragma unroll
    for (int m = 0; m < 50; m++) bufp[m] = 0ull;

    float vb[PFB];
#pragma unroll
    for (int i = 0; i < PFB; i++) vb[i] = __ldcs(pv + (size_t)i * BN);

    auto step = [&](int t, int c) {
        const int i8 = t & (PFB - 1);
        const float vt = vb[i8];
        if (t + PFB < T_STEPS) vb[i8] = __ldcs(pv + (size_t)(t + PFB) * BN);

        // refractory accumulator for this step (slot c, compile-time)
        float bacc;
        {
            unsigned long long pr = bufp[c >> 1];
            unsigned int u = (c & 1) ? (unsigned int)(pr >> 32) : (unsigned int)pr;
            bacc = __uint_as_float(u);
        }
        const float v = __fadd_rn(vt, bacc);  // v_eff = v_t + buf[0]

        // spike function, op-for-op vs reference
        const float nf   = floorf(fmaxf(v, 0.0f));
        const float e    = expf(__fmul_rn(fabsf(__fadd_rn(v, -1.0f)), -2.0f));
        const float sg   = __fmul_rn(2.0f, e);
        const float term = __fmul_rn(sg, v);
        const float nout = __fadd_rn(__fadd_rn(nf, -term), term);

        __stcs(po + (size_t)t * BN, nout);

        // zero slot c (becomes the slot for time t+100; rs[99]=0)
        bufp[c >> 1] &= (c & 1) ? 0x00000000FFFFFFFFull : 0xFFFFFFFF00000000ull;

        // buf update: slot s += fl(nout * rs[(s-c-1) mod 100]), packed f32x2.
        if (__any_sync(0xffffffffu, nout != 0.0f)) {
            unsigned long long n2;
            asm("mov.b64 %0, {%1, %2};" : "=l"(n2) : "f"(nout), "f"(nout));
            const int s0i = 99 - c;
            const int rr  = s0i & 3;
            const float* T = &RSD[rr][s0i - rr];
#pragma unroll
            for (int j = 0; j < 25; ++j) {
                const float4 rq = *(const float4*)(T + 4 * j);
                unsigned long long rsA, rsB, pA, pB, nA, nB;
                asm("mov.b64 %0, {%1, %2};" : "=l"(rsA) : "f"(rq.x), "f"(rq.y));
                asm("mov.b64 %0, {%1, %2};" : "=l"(rsB) : "f"(rq.z), "f"(rq.w));
                asm("mul.rn.f32x2 %0, %1, %2;" : "=l"(pA) : "l"(n2), "l"(rsA));
                asm("add.rn.f32x2 %0, %1, %2;" : "=l"(nA) : "l"(bufp[2 * j]), "l"(pA));
                bufp[2 * j] = nA;
                asm("mul.rn.f32x2 %0, %1, %2;" : "=l"(pB) : "l"(n2), "l"(rsB));
                asm("add.rn.f32x2 %0, %1, %2;" : "=l"(nB) : "l"(bufp[2 * j + 1]), "l"(pB));
                bufp[2 * j + 1] = nB;
            }
        }
    };

#pragma unroll 1
    for (int blk = 0; blk < 10; ++blk) {
        const int tb = blk * 100;
#pragma unroll
        for (int i = 0; i < 100; ++i) step(tb + i, i);
    }
#pragma unroll
    for (int i = 0; i < 24; ++i) step(1000 + i, i);
}

extern "C" void kernel_launch(void* const* d_in, const int* in_sizes, int n_in,
                              void* d_out, int out_size)
{
    const float* spikes = (const float*)d_in[0];
    const float* epsp   = (const float*)d_in[1];
    const float* refk   = (const float*)d_in[2];
    float* out = (float*)d_out;

    float* vt;
    cudaGetSymbolAddress((void**)&vt, VT);

    conv_kernel<<<BN * 2 / 128, 128>>>(spikes, epsp, vt);
    scan_kernel<<<BN / 128, 128>>>(vt, refk, out);
}